// round 1
// baseline (speedup 1.0000x reference)
#include <cuda_runtime.h>
#include <cuda_bf16.h>
#include <math.h>

// Problem: B=2, H=16, S=2048, DK=64
// Inputs (metadata order): Q[B,H,S,DK] f32, K[B,H,S,DK] f32, V[B,H,S,DK] f32, mask[B,1,S,S] i32
// Output: concat( output[B,H,S,DK] f32 , attn_weights[B,H,S,S] f32 )

#define BATCH 2
#define HEADS 16
#define SEQ   2048
#define DKDIM 64

// ---------------------------------------------------------------------------
// Pass 1: scores = scale * Q @ K^T, masked. Written raw into the weights
// region of d_out (softmax pass normalizes in place afterwards).
// Block: 256 threads computes a 64x64 tile of scores for one (b,h).
// grid: (S/64 ktiles, S/64 qtiles, B*H)
// ---------------------------------------------------------------------------
__global__ __launch_bounds__(256)
void sdpa_scores_kernel(const float* __restrict__ Q,
                        const float* __restrict__ K,
                        const int*   __restrict__ mask,
                        float* __restrict__ W)
{
    __shared__ float Qs[64][65];  // [d][q], pad 65 -> conflict-free
    __shared__ float Ks[64][65];  // [d][k]

    const int bh = blockIdx.z;
    const int b  = bh >> 4;            // H = 16
    const int q0 = blockIdx.y * 64;
    const int k0 = blockIdx.x * 64;
    const int tid = threadIdx.x;

    const float* Qp = Q + ((size_t)bh * SEQ + q0) * DKDIM;
    const float* Kp = K + ((size_t)bh * SEQ + k0) * DKDIM;

    // Cooperative transposed load: global row-major [r][d] -> smem [d][r]
    #pragma unroll
    for (int i = tid; i < 64 * 64; i += 256) {
        const int r = i >> 6;
        const int d = i & 63;
        Qs[d][r] = Qp[r * DKDIM + d];
        Ks[d][r] = Kp[r * DKDIM + d];
    }
    __syncthreads();

    const int tx = tid & 15;   // k direction (x4)
    const int ty = tid >> 4;   // q direction (x4)

    float acc[4][4] = {};
    #pragma unroll 16
    for (int d = 0; d < 64; d++) {
        float a[4], c[4];
        #pragma unroll
        for (int i = 0; i < 4; i++) a[i] = Qs[d][ty * 4 + i];
        #pragma unroll
        for (int j = 0; j < 4; j++) c[j] = Ks[d][tx * 4 + j];
        #pragma unroll
        for (int i = 0; i < 4; i++)
            #pragma unroll
            for (int j = 0; j < 4; j++)
                acc[i][j] = fmaf(a[i], c[j], acc[i][j]);
    }

    const float scale = 0.125f;  // 1/sqrt(64)
    #pragma unroll
    for (int i = 0; i < 4; i++) {
        const int q = q0 + ty * 4 + i;
        const size_t mrow = ((size_t)b * SEQ + q) * SEQ + k0;
        const size_t wrow = ((size_t)bh * SEQ + q) * SEQ + k0;
        #pragma unroll
        for (int j = 0; j < 4; j++) {
            const int kk = tx * 4 + j;
            const int m = mask[mrow + kk];
            const float v = (m == 0) ? -1e9f : acc[i][j] * scale;
            W[wrow + kk] = v;
        }
    }
}

// ---------------------------------------------------------------------------
// Pass 2: in-place row softmax over W (row length S = 2048).
// One block (256 threads) per row; 8 elements per thread in registers.
// ---------------------------------------------------------------------------
__global__ __launch_bounds__(256)
void sdpa_softmax_kernel(float* __restrict__ W)
{
    __shared__ float red[256];
    const size_t row = blockIdx.x;
    float* p = W + row * SEQ;
    const int tid = threadIdx.x;

    float v[8];
    float mx = -INFINITY;
    #pragma unroll
    for (int i = 0; i < 8; i++) {
        v[i] = p[tid + i * 256];
        mx = fmaxf(mx, v[i]);
    }
    red[tid] = mx;
    __syncthreads();
    #pragma unroll
    for (int s = 128; s > 0; s >>= 1) {
        if (tid < s) red[tid] = fmaxf(red[tid], red[tid + s]);
        __syncthreads();
    }
    mx = red[0];
    __syncthreads();

    float sum = 0.f;
    #pragma unroll
    for (int i = 0; i < 8; i++) {
        v[i] = __expf(v[i] - mx);
        sum += v[i];
    }
    red[tid] = sum;
    __syncthreads();
    #pragma unroll
    for (int s = 128; s > 0; s >>= 1) {
        if (tid < s) red[tid] += red[tid + s];
        __syncthreads();
    }
    const float inv = 1.0f / red[0];

    #pragma unroll
    for (int i = 0; i < 8; i++)
        p[tid + i * 256] = v[i] * inv;
}

// ---------------------------------------------------------------------------
// Pass 3: O = W @ V per (b,h). Block computes a 64(q) x 64(d) output tile,
// looping over S in 64-wide k-tiles.
// grid: (1, S/64 qtiles, B*H)
// ---------------------------------------------------------------------------
__global__ __launch_bounds__(256)
void sdpa_out_kernel(const float* __restrict__ W,
                     const float* __restrict__ V,
                     float* __restrict__ O)
{
    __shared__ float Ws[64][65];  // [k][q]
    __shared__ float Vs[64][65];  // [k][d]

    const int bh = blockIdx.z;
    const int q0 = blockIdx.y * 64;
    const int tid = threadIdx.x;

    const float* Wp = W + ((size_t)bh * SEQ + q0) * SEQ;
    const float* Vp = V + (size_t)bh * SEQ * DKDIM;

    const int tx = tid & 15;   // d direction (x4)
    const int ty = tid >> 4;   // q direction (x4)

    float acc[4][4] = {};

    for (int kt = 0; kt < SEQ; kt += 64) {
        #pragma unroll
        for (int i = tid; i < 64 * 64; i += 256) {
            const int r = i >> 6;
            const int c = i & 63;
            Ws[c][r] = Wp[(size_t)r * SEQ + kt + c];  // transpose: [q][k]->[k][q]
            Vs[r][c] = Vp[(kt + r) * DKDIM + c];      // [k][d]
        }
        __syncthreads();

        #pragma unroll 16
        for (int k = 0; k < 64; k++) {
            float a[4], c[4];
            #pragma unroll
            for (int i = 0; i < 4; i++) a[i] = Ws[k][ty * 4 + i];
            #pragma unroll
            for (int j = 0; j < 4; j++) c[j] = Vs[k][tx * 4 + j];
            #pragma unroll
            for (int i = 0; i < 4; i++)
                #pragma unroll
                for (int j = 0; j < 4; j++)
                    acc[i][j] = fmaf(a[i], c[j], acc[i][j]);
        }
        __syncthreads();
    }

    #pragma unroll
    for (int i = 0; i < 4; i++) {
        const int q = q0 + ty * 4 + i;
        float* orow = O + ((size_t)bh * SEQ + q) * DKDIM;
        #pragma unroll
        for (int j = 0; j < 4; j++)
            orow[tx * 4 + j] = acc[i][j];
    }
}

// ---------------------------------------------------------------------------
extern "C" void kernel_launch(void* const* d_in, const int* in_sizes, int n_in,
                              void* d_out, int out_size)
{
    const float* Q    = (const float*)d_in[0];
    const float* K    = (const float*)d_in[1];
    const float* V    = (const float*)d_in[2];
    const int*   mask = (const int*)  d_in[3];

    float* O = (float*)d_out;                                   // [B,H,S,DK]
    float* W = (float*)d_out + (size_t)BATCH * HEADS * SEQ * DKDIM;  // [B,H,S,S]

    // Pass 1: raw masked, scaled scores -> W region
    {
        dim3 grid(SEQ / 64, SEQ / 64, BATCH * HEADS);
        sdpa_scores_kernel<<<grid, 256>>>(Q, K, mask, W);
    }
    // Pass 2: in-place softmax over each row of W
    {
        dim3 grid(BATCH * HEADS * SEQ);
        sdpa_softmax_kernel<<<grid, 256>>>(W);
    }
    // Pass 3: O = W @ V
    {
        dim3 grid(1, SEQ / 64, BATCH * HEADS);
        sdpa_out_kernel<<<grid, 256>>>(W, V, O);
    }
}

// round 3
// speedup vs baseline: 2.2299x; 2.2299x over previous
#include <cuda_runtime.h>
#include <math.h>
#include <stdint.h>

// B=2, H=16, S=2048, DK=64
// Inputs: Q[B,H,S,DK] f32, K[B,H,S,DK] f32, V[B,H,S,DK] f32, mask[B,1,S,S] i32
// Output: concat( O[B,H,S,DK] f32, W[B,H,S,S] f32 )

#define BATCH 2
#define HEADS 16
#define SEQ   2048
#define DKDIM 64

// ---------------------------------------------------------------------------
// helpers
// ---------------------------------------------------------------------------
__device__ __forceinline__ float f2tf32(float x) {
    uint32_t u;
    asm("cvt.rna.tf32.f32 %0, %1;" : "=r"(u) : "f"(x));
    return __uint_as_float(u);
}

__device__ __forceinline__ void mma_tf32(float c[4],
                                         uint32_t a0, uint32_t a1, uint32_t a2, uint32_t a3,
                                         uint32_t b0, uint32_t b1) {
    asm volatile(
        "mma.sync.aligned.m16n8k8.row.col.f32.tf32.tf32.f32 "
        "{%0,%1,%2,%3}, {%4,%5,%6,%7}, {%8,%9}, {%0,%1,%2,%3};\n"
        : "+f"(c[0]), "+f"(c[1]), "+f"(c[2]), "+f"(c[3])
        : "r"(a0), "r"(a1), "r"(a2), "r"(a3), "r"(b0), "r"(b1));
}

// ---------------------------------------------------------------------------
// Pass 1: W_raw = mask ? scale*(Q K^T) : -1e9     (128q x 128k tile / block)
// 256 threads = 8 warps in 4(q) x 2(k); warp tile 32q x 64k.
// smem: Qs[128][68], Ks[128][68]  (stride 68 => fragment LDS bank-conflict-free)
// ---------------------------------------------------------------------------
#define SQ_STRIDE 68

__global__ __launch_bounds__(256)
void sdpa_scores_kernel(const float* __restrict__ Q,
                        const float* __restrict__ K,
                        const int*   __restrict__ mask,
                        float* __restrict__ W)
{
    extern __shared__ float smem[];
    float* Qs = smem;                      // [128][SQ_STRIDE]
    float* Ks = smem + 128 * SQ_STRIDE;    // [128][SQ_STRIDE]

    const int bh   = blockIdx.z;
    const int b    = bh >> 4;              // H = 16
    const int q0   = blockIdx.y * 128;
    const int k0   = blockIdx.x * 128;
    const int tid  = threadIdx.x;
    const int lane = tid & 31;
    const int warp = tid >> 5;
    const int wq   = warp >> 1;            // 0..3
    const int wk   = warp & 1;             // 0..1

    const float* Qp = Q + ((size_t)bh * SEQ + q0) * DKDIM;
    const float* Kp = K + ((size_t)bh * SEQ + k0) * DKDIM;

    // fill: 128 rows x (64/4)=16 float4 groups each array; tf32-round on store
    #pragma unroll
    for (int it = 0; it < 8; it++) {
        const int i = tid + it * 256;
        const int g = i & 15;
        const int r = i >> 4;
        float4 q4 = *(const float4*)(Qp + r * DKDIM + 4 * g);
        float4 k4 = *(const float4*)(Kp + r * DKDIM + 4 * g);
        float* qd = Qs + r * SQ_STRIDE + 4 * g;
        qd[0] = f2tf32(q4.x); qd[1] = f2tf32(q4.y);
        qd[2] = f2tf32(q4.z); qd[3] = f2tf32(q4.w);
        float* kd = Ks + r * SQ_STRIDE + 4 * g;
        kd[0] = f2tf32(k4.x); kd[1] = f2tf32(k4.y);
        kd[2] = f2tf32(k4.z); kd[3] = f2tf32(k4.w);
    }
    __syncthreads();

    float acc[2][8][4];
    #pragma unroll
    for (int i = 0; i < 2; i++)
        #pragma unroll
        for (int j = 0; j < 8; j++)
            #pragma unroll
            for (int t = 0; t < 4; t++) acc[i][j][t] = 0.f;

    const int qb  = wq * 32 + (lane >> 2);
    const int kb  = wk * 64 + (lane >> 2);
    const int dco = lane & 3;

    #pragma unroll
    for (int d0 = 0; d0 < DKDIM; d0 += 8) {
        uint32_t a[2][4];
        #pragma unroll
        for (int i = 0; i < 2; i++) {
            const float* base = Qs + (qb + i * 16) * SQ_STRIDE + d0 + dco;
            a[i][0] = __float_as_uint(base[0]);
            a[i][1] = __float_as_uint(base[8 * SQ_STRIDE]);
            a[i][2] = __float_as_uint(base[4]);
            a[i][3] = __float_as_uint(base[8 * SQ_STRIDE + 4]);
        }
        uint32_t bf[8][2];
        #pragma unroll
        for (int j = 0; j < 8; j++) {
            const float* base = Ks + (kb + j * 8) * SQ_STRIDE + d0 + dco;
            bf[j][0] = __float_as_uint(base[0]);
            bf[j][1] = __float_as_uint(base[4]);
        }
        #pragma unroll
        for (int i = 0; i < 2; i++)
            #pragma unroll
            for (int j = 0; j < 8; j++)
                mma_tf32(acc[i][j], a[i][0], a[i][1], a[i][2], a[i][3], bf[j][0], bf[j][1]);
    }

    // epilogue: scale + mask + write (float2 / int2, sector-aligned)
    const float scale = 0.125f;
    const int qrow0 = q0 + wq * 32 + (lane >> 2);
    const int kcol0 = k0 + wk * 64 + 2 * (lane & 3);
    #pragma unroll
    for (int i = 0; i < 2; i++) {
        #pragma unroll
        for (int rr = 0; rr < 2; rr++) {
            const int q = qrow0 + i * 16 + rr * 8;
            const int* mrow = mask + ((size_t)b * SEQ + q) * SEQ;
            float*    wrow = W    + ((size_t)bh * SEQ + q) * SEQ;
            #pragma unroll
            for (int j = 0; j < 8; j++) {
                const int kc = kcol0 + j * 8;
                int2 m = *(const int2*)(mrow + kc);
                float c0 = acc[i][j][rr * 2 + 0];
                float c1 = acc[i][j][rr * 2 + 1];
                float2 v;
                v.x = m.x ? c0 * scale : -1e9f;
                v.y = m.y ? c1 * scale : -1e9f;
                *(float2*)(wrow + kc) = v;
            }
        }
    }
}

// ---------------------------------------------------------------------------
// Pass 2: in-place row softmax; one block (256 thr) per row of 2048.
// ---------------------------------------------------------------------------
__global__ __launch_bounds__(256)
void sdpa_softmax_kernel(float* __restrict__ Wm)
{
    const size_t row = blockIdx.x;
    float4* p = (float4*)(Wm + row * SEQ);
    const int tid  = threadIdx.x;
    const int lane = tid & 31;
    const int warp = tid >> 5;
    __shared__ float sm[8];

    float4 v0 = p[tid];
    float4 v1 = p[tid + 256];

    float mx = fmaxf(fmaxf(fmaxf(v0.x, v0.y), fmaxf(v0.z, v0.w)),
                     fmaxf(fmaxf(v1.x, v1.y), fmaxf(v1.z, v1.w)));
    #pragma unroll
    for (int o = 16; o; o >>= 1) mx = fmaxf(mx, __shfl_xor_sync(0xffffffffu, mx, o));
    if (lane == 0) sm[warp] = mx;
    __syncthreads();
    mx = sm[0];
    #pragma unroll
    for (int w = 1; w < 8; w++) mx = fmaxf(mx, sm[w]);
    __syncthreads();

    v0.x = __expf(v0.x - mx); v0.y = __expf(v0.y - mx);
    v0.z = __expf(v0.z - mx); v0.w = __expf(v0.w - mx);
    v1.x = __expf(v1.x - mx); v1.y = __expf(v1.y - mx);
    v1.z = __expf(v1.z - mx); v1.w = __expf(v1.w - mx);

    float s = v0.x + v0.y + v0.z + v0.w + v1.x + v1.y + v1.z + v1.w;
    #pragma unroll
    for (int o = 16; o; o >>= 1) s += __shfl_xor_sync(0xffffffffu, s, o);
    if (lane == 0) sm[warp] = s;
    __syncthreads();
    s = sm[0];
    #pragma unroll
    for (int w = 1; w < 8; w++) s += sm[w];

    const float inv = 1.0f / s;
    v0.x *= inv; v0.y *= inv; v0.z *= inv; v0.w *= inv;
    v1.x *= inv; v1.y *= inv; v1.z *= inv; v1.w *= inv;
    p[tid]       = v0;
    p[tid + 256] = v1;
}

// ---------------------------------------------------------------------------
// Pass 3: O = W @ V.  Block: 64q x 64n, 128 threads = 4 warps 2(q)x2(n),
// warp tile 32x32; K loop over S in chunks of 64.
// smem strides: Ws 68, Vs 72 (both fragment patterns bank-conflict-free).
// ---------------------------------------------------------------------------
#define WS_STRIDE 68
#define VS_STRIDE 72

__global__ __launch_bounds__(128)
void sdpa_out_kernel(const float* __restrict__ W,
                     const float* __restrict__ V,
                     float* __restrict__ O)
{
    __shared__ float Ws[64 * WS_STRIDE];
    __shared__ float Vs[64 * VS_STRIDE];

    const int bh   = blockIdx.y;
    const int q0   = blockIdx.x * 64;
    const int tid  = threadIdx.x;
    const int lane = tid & 31;
    const int warp = tid >> 5;
    const int wq   = warp >> 1;   // 0..1
    const int wn   = warp & 1;    // 0..1

    const float* Wp = W + ((size_t)bh * SEQ + q0) * SEQ;
    const float* Vp = V + (size_t)bh * SEQ * DKDIM;

    float acc[2][4][4];
    #pragma unroll
    for (int i = 0; i < 2; i++)
        #pragma unroll
        for (int j = 0; j < 4; j++)
            #pragma unroll
            for (int t = 0; t < 4; t++) acc[i][j][t] = 0.f;

    for (int kc = 0; kc < SEQ; kc += 64) {
        // fill: 64 rows x 16 float4-groups each array; 1024 tasks / 128 thr
        #pragma unroll
        for (int it = 0; it < 8; it++) {
            const int i = tid + it * 128;
            const int g = i & 15;
            const int r = i >> 4;
            float4 w4 = *(const float4*)(Wp + (size_t)r * SEQ + kc + 4 * g);
            float4 v4 = *(const float4*)(Vp + (size_t)(kc + r) * DKDIM + 4 * g);
            float* wd = Ws + r * WS_STRIDE + 4 * g;
            wd[0] = f2tf32(w4.x); wd[1] = f2tf32(w4.y);
            wd[2] = f2tf32(w4.z); wd[3] = f2tf32(w4.w);
            float* vd = Vs + r * VS_STRIDE + 4 * g;
            vd[0] = f2tf32(v4.x); vd[1] = f2tf32(v4.y);
            vd[2] = f2tf32(v4.z); vd[3] = f2tf32(v4.w);
        }
        __syncthreads();

        #pragma unroll
        for (int k8 = 0; k8 < 64; k8 += 8) {
            uint32_t a[2][4];
            #pragma unroll
            for (int i = 0; i < 2; i++) {
                const float* base = Ws + (wq * 32 + i * 16 + (lane >> 2)) * WS_STRIDE + k8 + (lane & 3);
                a[i][0] = __float_as_uint(base[0]);
                a[i][1] = __float_as_uint(base[8 * WS_STRIDE]);
                a[i][2] = __float_as_uint(base[4]);
                a[i][3] = __float_as_uint(base[8 * WS_STRIDE + 4]);
            }
            uint32_t bf[4][2];
            #pragma unroll
            for (int j = 0; j < 4; j++) {
                const float* base = Vs + (k8 + (lane & 3)) * VS_STRIDE + wn * 32 + j * 8 + (lane >> 2);
                bf[j][0] = __float_as_uint(base[0]);
                bf[j][1] = __float_as_uint(base[4 * VS_STRIDE]);
            }
            #pragma unroll
            for (int i = 0; i < 2; i++)
                #pragma unroll
                for (int j = 0; j < 4; j++)
                    mma_tf32(acc[i][j], a[i][0], a[i][1], a[i][2], a[i][3], bf[j][0], bf[j][1]);
        }
        __syncthreads();
    }

    // epilogue
    #pragma unroll
    for (int i = 0; i < 2; i++) {
        #pragma unroll
        for (int rr = 0; rr < 2; rr++) {
            const int q = q0 + wq * 32 + i * 16 + rr * 8 + (lane >> 2);
            float* orow = O + ((size_t)bh * SEQ + q) * DKDIM + wn * 32;
            #pragma unroll
            for (int j = 0; j < 4; j++) {
                float2 v;
                v.x = acc[i][j][rr * 2 + 0];
                v.y = acc[i][j][rr * 2 + 1];
                *(float2*)(orow + j * 8 + 2 * (lane & 3)) = v;
            }
        }
    }
}

// ---------------------------------------------------------------------------
extern "C" void kernel_launch(void* const* d_in, const int* in_sizes, int n_in,
                              void* d_out, int out_size)
{
    const float* Q    = (const float*)d_in[0];
    const float* K    = (const float*)d_in[1];
    const float* V    = (const float*)d_in[2];
    const int*   mask = (const int*)  d_in[3];

    float* O = (float*)d_out;                                        // [B,H,S,DK]
    float* W = (float*)d_out + (size_t)BATCH * HEADS * SEQ * DKDIM;  // [B,H,S,S]

    const int scores_smem = 2 * 128 * SQ_STRIDE * sizeof(float);     // 69632 B
    cudaFuncSetAttribute(sdpa_scores_kernel,
                         cudaFuncAttributeMaxDynamicSharedMemorySize, scores_smem);

    {
        dim3 grid(SEQ / 128, SEQ / 128, BATCH * HEADS);
        sdpa_scores_kernel<<<grid, 256, scores_smem>>>(Q, K, mask, W);
    }
    {
        dim3 grid(BATCH * HEADS * SEQ);
        sdpa_softmax_kernel<<<grid, 256>>>(W);
    }
    {
        dim3 grid(SEQ / 64, BATCH * HEADS);
        sdpa_out_kernel<<<grid, 128>>>(W, V, O);
    }
}